// round 1
// baseline (speedup 1.0000x reference)
#include <cuda_runtime.h>
#include <math.h>

#define NC 24
#define B_   32
#define H4_  128
#define W4_  128
#define H5_  64
#define W5_  64
#define T4_  200
#define T5_  100

#define N4_  (B_*H4_*W4_)   // 524288
#define N5_  (B_*H5_*W5_)   // 131072

// Scratch (no cudaMalloc allowed): dedup masks + accumulators
__device__ unsigned char g_mask4[N4_];
__device__ unsigned char g_mask5[N5_];
// acc layout: [0]=lb4 [1]=lc4 [2]=lobj_pos4 [3]=negbce4 [4]=negcnt4
//             [5]=lb5 [6]=lc5 [7]=lobj_pos5 [8]=negbce5 [9]=negcnt5
__device__ double g_acc[10];

__device__ __forceinline__ float bce_logits(float x, float z) {
    // max(x,0) - x*z + log1p(exp(-|x|))
    return fmaxf(x, 0.0f) - x * z + log1pf(expf(-fabsf(x)));
}

__global__ void k_init() {
    int tid = blockIdx.x * blockDim.x + threadIdx.x;
    int stride = gridDim.x * blockDim.x;
    for (int j = tid; j < N4_; j += stride) g_mask4[j] = 0;
    for (int j = tid; j < N5_; j += stride) g_mask5[j] = 0;
    if (blockIdx.x == 0 && threadIdx.x < 10) g_acc[threadIdx.x] = 0.0;
}

// One thread per target. accBase: 0 for p4, 5 for p5.
__global__ void k_targets(const float* __restrict__ cls,
                          const float* __restrict__ reg,
                          const float* __restrict__ tgt,
                          unsigned char* __restrict__ mask,
                          int Tn, int H, int W, int accBase) {
    int i = blockIdx.x * blockDim.x + threadIdx.x;
    int total = B_ * Tn;
    if (i >= total) return;
    int b = i / Tn;
    const float* t = tgt + (size_t)i * 6;

    int   tcls = (int)t[0];
    float tx = t[1] * (float)W;
    float ty = t[2] * (float)H;
    float tw = t[3] * (float)W;
    float th = t[4] * (float)H;

    int gx = min(max((int)tx, 0), W - 1);
    int gy = min(max((int)ty, 0), H - 1);

    size_t hw = (size_t)H * W;
    size_t cell = (size_t)gy * W + gx;

    // reg gather: (B,4,H,W)
    size_t rb = (size_t)b * 4 * hw + cell;
    float r0 = reg[rb];
    float r1 = reg[rb + hw];
    float r2 = reg[rb + 2 * hw];
    float r3 = reg[rb + 3 * hw];

    float px = fminf(fmaxf((float)gx + r0, 0.0f), (float)W);
    float py = fminf(fmaxf((float)gy + r1, 0.0f), (float)H);
    float pw = fminf(fmaxf(expf(r2), 1.0f), (float)W) * 0.1f;
    float ph = fminf(fmaxf(expf(r3), 1.0f), (float)H) * 0.1f;

    float pb0 = px - pw * 0.5f, pb1 = py - ph * 0.5f;
    float pb2 = px + pw * 0.5f, pb3 = py + ph * 0.5f;
    float tb0 = tx - tw * 0.5f, tb1 = ty - th * 0.5f;
    float tb2 = tx + tw * 0.5f, tb3 = ty + th * 0.5f;

    float sl1 = 0.0f;
    {
        float d, ad;
        d = pb0 - tb0; ad = fabsf(d); sl1 += (ad < 1.0f) ? 0.5f * d * d : (ad - 0.5f);
        d = pb1 - tb1; ad = fabsf(d); sl1 += (ad < 1.0f) ? 0.5f * d * d : (ad - 0.5f);
        d = pb2 - tb2; ad = fabsf(d); sl1 += (ad < 1.0f) ? 0.5f * d * d : (ad - 0.5f);
        d = pb3 - tb3; ad = fabsf(d); sl1 += (ad < 1.0f) ? 0.5f * d * d : (ad - 0.5f);
    }
    sl1 *= 0.25f;  // mean over 4 coords

    // cls gather: (B, 1+NC, H, W), channel 0 = objectness
    size_t cb = (size_t)b * (1 + NC) * hw + cell;
    float obj = cls[cb];
    float lobj = bce_logits(obj, 1.0f);

    float lcls = 0.0f;
    bool valid = (tcls < NC);
    #pragma unroll
    for (int c = 0; c < NC; c++) {
        float x = cls[cb + (size_t)(c + 1) * hw];
        float o = (valid && c == tcls) ? 1.0f : 0.0f;
        float bce = bce_logits(x, o);
        float p = 1.0f / (1.0f + expf(-x));
        float pt = p * o + (1.0f - p) * (1.0f - o);
        float om = 1.0f - pt;
        lcls += 0.25f * om * om * bce;
    }
    lcls *= (1.0f / (float)NC);

    // mark positive cell (dedup set semantics; races benign, all write 1)
    mask[(size_t)b * hw + cell] = 1;

    atomicAdd(&g_acc[accBase + 0], (double)sl1);
    atomicAdd(&g_acc[accBase + 1], (double)lcls);
    atomicAdd(&g_acc[accBase + 2], (double)lobj);
}

// Full-grid negative objectness pass over BOTH scales in one kernel.
__global__ void k_neg(const float* __restrict__ cls4,
                      const float* __restrict__ cls5) {
    const int total = N4_ + N5_;
    int i = blockIdx.x * blockDim.x + threadIdx.x;

    float s4 = 0.0f, c4 = 0.0f, s5 = 0.0f, c5 = 0.0f;
    if (i < total) {
        if (i < N4_) {
            int b = i / (H4_ * W4_);
            int pos = i - b * (H4_ * W4_);
            if (!g_mask4[i]) {
                float x = cls4[(size_t)b * (1 + NC) * (H4_ * W4_) + pos];
                s4 = bce_logits(x, 0.0f);
                c4 = 1.0f;
            }
        } else {
            int j = i - N4_;
            int b = j / (H5_ * W5_);
            int pos = j - b * (H5_ * W5_);
            if (!g_mask5[j]) {
                float x = cls5[(size_t)b * (1 + NC) * (H5_ * W5_) + pos];
                s5 = bce_logits(x, 0.0f);
                c5 = 1.0f;
            }
        }
    }

    // warp reduce
    #pragma unroll
    for (int off = 16; off > 0; off >>= 1) {
        s4 += __shfl_down_sync(0xFFFFFFFFu, s4, off);
        c4 += __shfl_down_sync(0xFFFFFFFFu, c4, off);
        s5 += __shfl_down_sync(0xFFFFFFFFu, s5, off);
        c5 += __shfl_down_sync(0xFFFFFFFFu, c5, off);
    }

    __shared__ float sh[4][8];  // up to 8 warps @ 256 threads
    int lane = threadIdx.x & 31;
    int warp = threadIdx.x >> 5;
    if (lane == 0) { sh[0][warp] = s4; sh[1][warp] = c4; sh[2][warp] = s5; sh[3][warp] = c5; }
    __syncthreads();

    if (warp == 0) {
        int nw = (blockDim.x + 31) >> 5;
        float a = (lane < nw) ? sh[0][lane] : 0.0f;
        float b = (lane < nw) ? sh[1][lane] : 0.0f;
        float c = (lane < nw) ? sh[2][lane] : 0.0f;
        float d = (lane < nw) ? sh[3][lane] : 0.0f;
        #pragma unroll
        for (int off = 4; off > 0; off >>= 1) {
            a += __shfl_down_sync(0xFFFFFFFFu, a, off);
            b += __shfl_down_sync(0xFFFFFFFFu, b, off);
            c += __shfl_down_sync(0xFFFFFFFFu, c, off);
            d += __shfl_down_sync(0xFFFFFFFFu, d, off);
        }
        if (lane == 0) {
            if (a != 0.0f || b != 0.0f) { atomicAdd(&g_acc[3], (double)a); atomicAdd(&g_acc[4], (double)b); }
            if (c != 0.0f || d != 0.0f) { atomicAdd(&g_acc[8], (double)c); atomicAdd(&g_acc[9], (double)d); }
        }
    }
}

__global__ void k_final(float* out) {
    double n = (double)(B_ * T4_ + B_ * T5_);
    double lb = (g_acc[0] + g_acc[5]) / n;
    double lc = (g_acc[1] + g_acc[6]) / n;
    double lo4 = g_acc[2] + g_acc[3] / g_acc[4] * 0.5;
    double lo5 = g_acc[7] + g_acc[8] / g_acc[9] * 0.5;
    double total_grid = (double)(N4_ + N5_);
    double lo = (lo4 + lo5) / (total_grid + 1e-8);
    out[0] = (float)(lb + lo + lc);
    out[1] = (float)lb;
    out[2] = (float)lo;
    out[3] = (float)lc;
}

extern "C" void kernel_launch(void* const* d_in, const int* in_sizes, int n_in,
                              void* d_out, int out_size) {
    const float* cls4 = (const float*)d_in[0];
    const float* reg4 = (const float*)d_in[1];
    const float* cls5 = (const float*)d_in[2];
    const float* reg5 = (const float*)d_in[3];
    const float* tgt4 = (const float*)d_in[4];
    const float* tgt5 = (const float*)d_in[5];
    float* out = (float*)d_out;

    unsigned char* m4;
    unsigned char* m5;
    cudaGetSymbolAddress((void**)&m4, g_mask4);
    cudaGetSymbolAddress((void**)&m5, g_mask5);

    k_init<<<512, 256>>>();

    int tot4 = B_ * T4_;
    int tot5 = B_ * T5_;
    k_targets<<<(tot4 + 127) / 128, 128>>>(cls4, reg4, tgt4, m4, T4_, H4_, W4_, 0);
    k_targets<<<(tot5 + 127) / 128, 128>>>(cls5, reg5, tgt5, m5, T5_, H5_, W5_, 5);

    int totNeg = N4_ + N5_;
    k_neg<<<(totNeg + 255) / 256, 256>>>(cls4, cls5);

    k_final<<<1, 1>>>(out);
}

// round 2
// speedup vs baseline: 3.9189x; 3.9189x over previous
#include <cuda_runtime.h>
#include <math.h>

#define NC 24
#define B_   32
#define H4_  128
#define W4_  128
#define H5_  64
#define W5_  64
#define T4_  200
#define T5_  100

#define HW4  (H4_*W4_)          // 16384
#define HW5  (H5_*W5_)          // 4096
#define N4_  (B_*HW4)           // 524288
#define N5_  (B_*HW5)           // 131072

#define MW4  (N4_/32)           // 16384 u32 bitmask words
#define MW5  (N5_/32)           // 4096

// Block partition of the fused kernel
#define NB4S 128                // grid4 streaming blocks
#define NB5S 32                 // grid5 streaming blocks
#define NBT4 800                // p4 targets: 6400 warps / 8 per block
#define NBT5 400                // p5 targets: 3200 warps / 8 per block
#define NB_TOTAL (NB4S + NB5S + NBT4 + NBT5)   // 1360

// Scratch (no cudaMalloc allowed)
__device__ unsigned int g_bits4[MW4];
__device__ unsigned int g_bits5[MW5];
// acc: [0]=lb4 [1]=lc4 [2]=lobjpos4 [3]=negbce4(stream - corr) [4]=winnercnt4
//      [5]=lb5 [6]=lc5 [7]=lobjpos5 [8]=negbce5               [9]=winnercnt5
__device__ double g_acc[10];

__device__ __forceinline__ float bce0(float x) {          // bce(x, 0)
    return fmaxf(x, 0.0f) + log1pf(__expf(-fabsf(x)));
}
__device__ __forceinline__ float bce1(float x) {          // bce(x, 1)
    return fmaxf(x, 0.0f) - x + log1pf(__expf(-fabsf(x)));
}

__global__ void k_init() {
    int tid = blockIdx.x * blockDim.x + threadIdx.x;
    int stride = gridDim.x * blockDim.x;
    for (int j = tid; j < MW4; j += stride) g_bits4[j] = 0u;
    for (int j = tid; j < MW5; j += stride) g_bits5[j] = 0u;
    if (blockIdx.x == 0 && threadIdx.x < 10) g_acc[threadIdx.x] = 0.0;
}

// ---------------------------------------------------------------------------
// Fused kernel: streaming negative-objectness over both full grids +
// warp-per-target positive losses with bitmask dedup corrections.
// ---------------------------------------------------------------------------
__global__ void __launch_bounds__(256) k_main(
    const float* __restrict__ cls4, const float* __restrict__ reg4,
    const float* __restrict__ cls5, const float* __restrict__ reg5,
    const float* __restrict__ tgt4, const float* __restrict__ tgt5)
{
    const int bx = blockIdx.x;
    const int lane = threadIdx.x & 31;
    const int warp = threadIdx.x >> 5;

    __shared__ float sh0[8], sh1[8], sh2[8], sh3[8], sh4[8];

    if (bx < NB4S + NB5S) {
        // ---------------- streaming section: sum bce(x,0) over all cells ----
        float s = 0.0f;
        if (bx < NB4S) {
            int tid = bx * 256 + threadIdx.x;
            const int nvec = N4_ / 4;                     // 131072 float4
            for (int v = tid; v < nvec; v += NB4S * 256) {
                int b = v >> 12;                          // 4096 vecs per image
                int pos = (v & 4095) * 4;
                const float4 x = *(const float4*)(cls4 + (size_t)b * (1 + NC) * HW4 + pos);
                s += bce0(x.x) + bce0(x.y) + bce0(x.z) + bce0(x.w);
            }
        } else {
            int tid = (bx - NB4S) * 256 + threadIdx.x;
            const int nvec = N5_ / 4;                     // 32768 float4
            for (int v = tid; v < nvec; v += NB5S * 256) {
                int b = v >> 10;                          // 1024 vecs per image
                int pos = (v & 1023) * 4;
                const float4 x = *(const float4*)(cls5 + (size_t)b * (1 + NC) * HW5 + pos);
                s += bce0(x.x) + bce0(x.y) + bce0(x.z) + bce0(x.w);
            }
        }
        #pragma unroll
        for (int off = 16; off > 0; off >>= 1) s += __shfl_down_sync(0xFFFFFFFFu, s, off);
        if (lane == 0) sh0[warp] = s;
        __syncthreads();
        if (warp == 0) {
            float a = (lane < 8) ? sh0[lane] : 0.0f;
            #pragma unroll
            for (int off = 4; off > 0; off >>= 1) a += __shfl_down_sync(0xFFFFFFFFu, a, off);
            if (lane == 0) atomicAdd(&g_acc[(bx < NB4S) ? 3 : 8], (double)a);
        }
        return;
    }

    // ---------------- target section: one warp per target -------------------
    bool is4 = (bx < NB4S + NB5S + NBT4);
    int tblock = is4 ? (bx - NB4S - NB5S) : (bx - NB4S - NB5S - NBT4);
    int widx = tblock * 8 + warp;                         // global target index

    const int Tn = is4 ? T4_ : T5_;
    const int H  = is4 ? H4_ : H5_;
    const int W  = is4 ? W4_ : W5_;
    const int hw = is4 ? HW4 : HW5;
    const float* cls = is4 ? cls4 : cls5;
    const float* reg = is4 ? reg4 : reg5;
    const float* tgt = is4 ? tgt4 : tgt5;
    unsigned int* bits = is4 ? g_bits4 : g_bits5;

    int b = widx / Tn;
    const float* t = tgt + (size_t)widx * 6;

    // uniform loads (broadcast through L1)
    int   tcls = (int)t[0];
    float tx = t[1] * (float)W;
    float ty = t[2] * (float)H;
    float tw = t[3] * (float)W;
    float th = t[4] * (float)H;

    int gx = min(max((int)tx, 0), W - 1);
    int gy = min(max((int)ty, 0), H - 1);
    int cell = gy * W + gx;
    size_t cb = (size_t)b * (1 + NC) * hw + cell;

    float v_cls = 0.0f;           // per-lane focal term (lanes 0..23)
    float v_obj = 0.0f, v_sl1 = 0.0f, v_cs = 0.0f, v_cc = 0.0f;

    if (lane < NC) {
        float x = cls[cb + (size_t)(lane + 1) * hw];
        float p = 1.0f / (1.0f + __expf(-x));
        bool hit = (lane == tcls);
        float bce = hit ? bce1(x) : bce0(x);
        float pt  = hit ? p : (1.0f - p);
        float om  = 1.0f - pt;
        v_cls = (0.25f / (float)NC) * om * om * bce;
    } else if (lane == 24) {
        float obj = cls[cb];
        v_obj = bce1(obj);
        // dedup: winner corrects the streaming neg sum
        int bitidx = b * hw + cell;
        unsigned int m = 1u << (bitidx & 31);
        unsigned int old = atomicOr(&bits[bitidx >> 5], m);
        if (!(old & m)) { v_cs = -bce0(obj); v_cc = 1.0f; }
    } else if (lane == 25) {
        size_t rb = (size_t)b * 4 * hw + cell;
        float r0 = reg[rb];
        float r1 = reg[rb + hw];
        float r2 = reg[rb + 2 * (size_t)hw];
        float r3 = reg[rb + 3 * (size_t)hw];
        float px = fminf(fmaxf((float)gx + r0, 0.0f), (float)W);
        float py = fminf(fmaxf((float)gy + r1, 0.0f), (float)H);
        float pw = fminf(fmaxf(__expf(r2), 1.0f), (float)W) * 0.1f;
        float ph = fminf(fmaxf(__expf(r3), 1.0f), (float)H) * 0.1f;
        float pb0 = px - pw * 0.5f, pb1 = py - ph * 0.5f;
        float pb2 = px + pw * 0.5f, pb3 = py + ph * 0.5f;
        float tb0 = tx - tw * 0.5f, tb1 = ty - th * 0.5f;
        float tb2 = tx + tw * 0.5f, tb3 = ty + th * 0.5f;
        float d, ad, s = 0.0f;
        d = pb0 - tb0; ad = fabsf(d); s += (ad < 1.0f) ? 0.5f * d * d : (ad - 0.5f);
        d = pb1 - tb1; ad = fabsf(d); s += (ad < 1.0f) ? 0.5f * d * d : (ad - 0.5f);
        d = pb2 - tb2; ad = fabsf(d); s += (ad < 1.0f) ? 0.5f * d * d : (ad - 0.5f);
        d = pb3 - tb3; ad = fabsf(d); s += (ad < 1.0f) ? 0.5f * d * d : (ad - 0.5f);
        v_sl1 = s * 0.25f;
    }

    // warp reduce cls focal sum (only lanes 0..23 nonzero)
    #pragma unroll
    for (int off = 16; off > 0; off >>= 1) v_cls += __shfl_down_sync(0xFFFFFFFFu, v_cls, off);

    if (lane == 0)  sh0[warp] = v_cls;
    if (lane == 24) { sh1[warp] = v_obj; sh3[warp] = v_cs; sh4[warp] = v_cc; }
    if (lane == 25) sh2[warp] = v_sl1;
    __syncthreads();

    if (warp == 0) {
        float a0 = (lane < 8) ? sh0[lane] : 0.0f;
        float a1 = (lane < 8) ? sh1[lane] : 0.0f;
        float a2 = (lane < 8) ? sh2[lane] : 0.0f;
        float a3 = (lane < 8) ? sh3[lane] : 0.0f;
        float a4 = (lane < 8) ? sh4[lane] : 0.0f;
        #pragma unroll
        for (int off = 4; off > 0; off >>= 1) {
            a0 += __shfl_down_sync(0xFFFFFFFFu, a0, off);
            a1 += __shfl_down_sync(0xFFFFFFFFu, a1, off);
            a2 += __shfl_down_sync(0xFFFFFFFFu, a2, off);
            a3 += __shfl_down_sync(0xFFFFFFFFu, a3, off);
            a4 += __shfl_down_sync(0xFFFFFFFFu, a4, off);
        }
        if (lane == 0) {
            int base = is4 ? 0 : 5;
            atomicAdd(&g_acc[base + 0], (double)a2);   // bbox
            atomicAdd(&g_acc[base + 1], (double)a0);   // cls focal
            atomicAdd(&g_acc[base + 2], (double)a1);   // obj positive
            atomicAdd(&g_acc[base + 3], (double)a3);   // neg bce correction
            atomicAdd(&g_acc[base + 4], (double)a4);   // winner count
        }
    }
}

__global__ void k_final(float* out) {
    double n = (double)(B_ * T4_ + B_ * T5_);
    double lb = (g_acc[0] + g_acc[5]) / n;
    double lc = (g_acc[1] + g_acc[6]) / n;
    double cnt4 = (double)N4_ - g_acc[4];
    double cnt5 = (double)N5_ - g_acc[9];
    double lo4 = g_acc[2] + g_acc[3] / cnt4 * 0.5;
    double lo5 = g_acc[7] + g_acc[8] / cnt5 * 0.5;
    double lo = (lo4 + lo5) / ((double)(N4_ + N5_) + 1e-8);
    out[0] = (float)(lb + lo + lc);
    out[1] = (float)lb;
    out[2] = (float)lo;
    out[3] = (float)lc;
}

extern "C" void kernel_launch(void* const* d_in, const int* in_sizes, int n_in,
                              void* d_out, int out_size) {
    const float* cls4 = (const float*)d_in[0];
    const float* reg4 = (const float*)d_in[1];
    const float* cls5 = (const float*)d_in[2];
    const float* reg5 = (const float*)d_in[3];
    const float* tgt4 = (const float*)d_in[4];
    const float* tgt5 = (const float*)d_in[5];
    float* out = (float*)d_out;

    k_init<<<80, 256>>>();
    k_main<<<NB_TOTAL, 256>>>(cls4, reg4, cls5, reg5, tgt4, tgt5);
    k_final<<<1, 1>>>(out);
}

// round 3
// speedup vs baseline: 4.3939x; 1.1212x over previous
#include <cuda_runtime.h>
#include <math.h>

#define NC 24
#define B_   32
#define H4_  128
#define W4_  128
#define H5_  64
#define W5_  64
#define T4_  200
#define T5_  100

#define HW4  (H4_*W4_)          // 16384
#define HW5  (H5_*W5_)          // 4096
#define N4_  (B_*HW4)           // 524288
#define N5_  (B_*HW5)           // 131072
#define NT4  (B_*T4_)           // 6400
#define NT5  (B_*T5_)           // 3200

#define NB_S   80               // streaming blocks (512 thr)
#define NBT    600              // target blocks: 9600 warps / 16
#define NB_TOTAL (NB_S + NBT)   // 680

// acc: [0]=lb4 [1]=lc4 [2]=lobjpos4 [3]=negbce4 [4]=wincnt4
//      [5]=lb5 [6]=lc5 [7]=lobjpos5 [8]=negbce5 [9]=wincnt5
__device__ double g_acc[10];          // zero-init at load; self-cleaned by finalize
__device__ unsigned int g_ticket;     // zero-init; self-cleaned

__device__ __forceinline__ float bce0(float x) {   // bce(x, 0)
    return fmaxf(x, 0.0f) + __logf(1.0f + __expf(-fabsf(x)));
}
__device__ __forceinline__ float bce1(float x) {   // bce(x, 1) = bce0(x) - x
    return bce0(x) - x;
}

__global__ void __launch_bounds__(512) k_main(
    const float* __restrict__ cls4, const float* __restrict__ reg4,
    const float* __restrict__ cls5, const float* __restrict__ reg5,
    const float* __restrict__ tgt4, const float* __restrict__ tgt5,
    float* __restrict__ out)
{
    const int bx   = blockIdx.x;
    const int lane = threadIdx.x & 31;
    const int warp = threadIdx.x >> 5;

    __shared__ float sh[10][16];

    if (bx < NB_S) {
        // ------------- streaming: sum bce(x,0) over ALL grid cells ----------
        float s4 = 0.0f, s5 = 0.0f;
        const int NV4 = N4_ / 4;                  // 131072 float4
        const int NV  = (N4_ + N5_) / 4;          // 163840
        for (int v = bx * 512 + threadIdx.x; v < NV; v += NB_S * 512) {
            if (v < NV4) {
                int b = v >> 12;                  // 4096 vecs / image
                int pos = (v & 4095) * 4;
                const float4 x = *(const float4*)(cls4 + (size_t)b * (1 + NC) * HW4 + pos);
                s4 += bce0(x.x) + bce0(x.y) + bce0(x.z) + bce0(x.w);
            } else {
                int v5 = v - NV4;
                int b = v5 >> 10;                 // 1024 vecs / image
                int pos = (v5 & 1023) * 4;
                const float4 x = *(const float4*)(cls5 + (size_t)b * (1 + NC) * HW5 + pos);
                s5 += bce0(x.x) + bce0(x.y) + bce0(x.z) + bce0(x.w);
            }
        }
        #pragma unroll
        for (int off = 16; off > 0; off >>= 1) {
            s4 += __shfl_down_sync(0xFFFFFFFFu, s4, off);
            s5 += __shfl_down_sync(0xFFFFFFFFu, s5, off);
        }
        if (lane == 0) { sh[0][warp] = s4; sh[1][warp] = s5; }
        __syncthreads();
        if (warp == 0) {
            float a = (lane < 16) ? sh[0][lane] : 0.0f;
            float c = (lane < 16) ? sh[1][lane] : 0.0f;
            #pragma unroll
            for (int off = 8; off > 0; off >>= 1) {
                a += __shfl_down_sync(0xFFFFFFFFu, a, off);
                c += __shfl_down_sync(0xFFFFFFFFu, c, off);
            }
            if (lane == 0) { atomicAdd(&g_acc[3], (double)a); atomicAdd(&g_acc[8], (double)c); }
        }
        __syncthreads();
    } else {
        // ------------- targets: one warp per target -------------------------
        // zero the reduction scratch
        if (threadIdx.x < 160) ((float*)sh)[threadIdx.x] = 0.0f;
        __syncthreads();

        int widx = (bx - NB_S) * 16 + warp;       // 0..9599
        bool is4 = (widx < NT4);
        int tw   = is4 ? widx : (widx - NT4);

        const int Tn = is4 ? T4_ : T5_;
        const int H  = is4 ? H4_ : H5_;
        const int W  = is4 ? W4_ : W5_;
        const int hw = is4 ? HW4 : HW5;
        const float* cls = is4 ? cls4 : cls5;
        const float* reg = is4 ? reg4 : reg5;
        const float* tgt = is4 ? tgt4 : tgt5;

        int b  = tw / Tn;
        int il = tw - b * Tn;                     // index within image
        const float* t = tgt + (size_t)tw * 6;

        int   tcls = (int)t[0];
        float tx = t[1] * (float)W;
        float ty = t[2] * (float)H;
        float twd = t[3] * (float)W;
        float thd = t[4] * (float)H;

        int gx = min(max((int)tx, 0), W - 1);
        int gy = min(max((int)ty, 0), H - 1);
        int cell = gy * W + gx;

        // ---- dedup scan: winner iff no earlier target in this image shares the cell
        bool dup = false;
        const float* tbase = tgt + (size_t)b * Tn * 6;
        for (int j0 = 0; j0 < il; j0 += 32) {
            int j = j0 + lane;
            bool d = false;
            if (j < il) {
                float txj = tbase[(size_t)j * 6 + 1] * (float)W;
                float tyj = tbase[(size_t)j * 6 + 2] * (float)H;
                int gxj = min(max((int)txj, 0), W - 1);
                int gyj = min(max((int)tyj, 0), H - 1);
                d = (gyj * W + gxj) == cell;
            }
            dup |= d;
        }
        dup = __any_sync(0xFFFFFFFFu, dup);       // warp-uniform

        size_t cb = (size_t)b * (1 + NC) * hw + cell;

        float v_cls = 0.0f, v_obj = 0.0f, v_sl1 = 0.0f, v_cs = 0.0f, v_cc = 0.0f;

        if (lane < NC) {
            float x = cls[cb + (size_t)(lane + 1) * hw];
            float p = 1.0f / (1.0f + __expf(-x));
            bool hit = (lane == tcls);
            float bce = hit ? bce1(x) : bce0(x);
            float pt  = hit ? p : (1.0f - p);
            float om  = 1.0f - pt;
            v_cls = (0.25f / (float)NC) * om * om * bce;
        } else if (lane == 24) {
            float obj = cls[cb];
            v_obj = bce1(obj);
            if (!dup) { v_cs = -bce0(obj); v_cc = 1.0f; }
        } else if (lane == 25) {
            size_t rb = (size_t)b * 4 * hw + cell;
            float r0 = reg[rb];
            float r1 = reg[rb + hw];
            float r2 = reg[rb + 2 * (size_t)hw];
            float r3 = reg[rb + 3 * (size_t)hw];
            float px = fminf(fmaxf((float)gx + r0, 0.0f), (float)W);
            float py = fminf(fmaxf((float)gy + r1, 0.0f), (float)H);
            float pw = fminf(fmaxf(__expf(r2), 1.0f), (float)W) * 0.1f;
            float ph = fminf(fmaxf(__expf(r3), 1.0f), (float)H) * 0.1f;
            float pb0 = px - pw * 0.5f, pb1 = py - ph * 0.5f;
            float pb2 = px + pw * 0.5f, pb3 = py + ph * 0.5f;
            float tb0 = tx - twd * 0.5f, tb1 = ty - thd * 0.5f;
            float tb2 = tx + twd * 0.5f, tb3 = ty + thd * 0.5f;
            float d, ad, s = 0.0f;
            d = pb0 - tb0; ad = fabsf(d); s += (ad < 1.0f) ? 0.5f * d * d : (ad - 0.5f);
            d = pb1 - tb1; ad = fabsf(d); s += (ad < 1.0f) ? 0.5f * d * d : (ad - 0.5f);
            d = pb2 - tb2; ad = fabsf(d); s += (ad < 1.0f) ? 0.5f * d * d : (ad - 0.5f);
            d = pb3 - tb3; ad = fabsf(d); s += (ad < 1.0f) ? 0.5f * d * d : (ad - 0.5f);
            v_sl1 = s * 0.25f;
        }

        // reduce focal across lanes 0..23
        #pragma unroll
        for (int off = 16; off > 0; off >>= 1)
            v_cls += __shfl_down_sync(0xFFFFFFFFu, v_cls, off);

        int base = is4 ? 0 : 5;
        if (lane == 0)  sh[base + 0][warp] = v_sl1 == v_sl1 ? 0.0f : 0.0f; // placeholder overwritten below
        // write the 5 quantities (from the lanes that hold them)
        if (lane == 25) sh[base + 0][warp] = v_sl1;
        if (lane == 0)  sh[base + 1][warp] = v_cls;
        if (lane == 24) { sh[base + 2][warp] = v_obj; sh[base + 3][warp] = v_cs; sh[base + 4][warp] = v_cc; }
        __syncthreads();

        // warps 0..9 each reduce one accumulator row
        if (warp < 10) {
            float a = (lane < 16) ? sh[warp][lane] : 0.0f;
            #pragma unroll
            for (int off = 8; off > 0; off >>= 1)
                a += __shfl_down_sync(0xFFFFFFFFu, a, off);
            if (lane == 0 && a != 0.0f) atomicAdd(&g_acc[warp], (double)a);
        }
        __syncthreads();
    }

    // ------------- last-block finalize (self-cleaning state) ----------------
    if (threadIdx.x == 0) {
        __threadfence();
        unsigned int old = atomicAdd(&g_ticket, 1u);
        if (old == NB_TOTAL - 1) {
            __threadfence();
            volatile double* acc = g_acc;
            double n  = (double)(NT4 + NT5);
            double lb = (acc[0] + acc[5]) / n;
            double lc = (acc[1] + acc[6]) / n;
            double cnt4 = (double)N4_ - acc[4];
            double cnt5 = (double)N5_ - acc[9];
            double lo4 = acc[2] + acc[3] / cnt4 * 0.5;
            double lo5 = acc[7] + acc[8] / cnt5 * 0.5;
            double lo = (lo4 + lo5) / ((double)(N4_ + N5_) + 1e-8);
            out[0] = (float)(lb + lo + lc);
            out[1] = (float)lb;
            out[2] = (float)lo;
            out[3] = (float)lc;
            // reset state for next (graph-replayed) invocation
            #pragma unroll
            for (int i = 0; i < 10; i++) acc[i] = 0.0;
            __threadfence();
            *(volatile unsigned int*)&g_ticket = 0u;
        }
    }
}

extern "C" void kernel_launch(void* const* d_in, const int* in_sizes, int n_in,
                              void* d_out, int out_size) {
    const float* cls4 = (const float*)d_in[0];
    const float* reg4 = (const float*)d_in[1];
    const float* cls5 = (const float*)d_in[2];
    const float* reg5 = (const float*)d_in[3];
    const float* tgt4 = (const float*)d_in[4];
    const float* tgt5 = (const float*)d_in[5];
    float* out = (float*)d_out;

    k_main<<<NB_TOTAL, 512>>>(cls4, reg4, cls5, reg5, tgt4, tgt5, out);
}

// round 5
// speedup vs baseline: 4.9153x; 1.1186x over previous
#include <cuda_runtime.h>
#include <math.h>

#define NC 24
#define B_   32
#define H4_  128
#define W4_  128
#define H5_  64
#define W5_  64
#define T4_  200
#define T5_  100

#define HW4  (H4_*W4_)          // 16384
#define HW5  (H5_*W5_)          // 4096
#define N4_  (B_*HW4)           // 524288
#define N5_  (B_*HW5)           // 131072
#define NT4  (B_*T4_)           // 6400
#define NT5  (B_*T5_)           // 3200
#define NTT  (NT4+NT5)          // 9600

#define NBT   300               // target blocks: 16 warps x 2 targets = 32/block
#define NB_S  160               // streaming blocks
#define NB_TOTAL (NBT + NB_S)   // 460

// acc: [0]=lb4 [1]=lc4 [2]=lobjpos4 [3]=negbce4 [4]=wincnt4
//      [5]=lb5 [6]=lc5 [7]=lobjpos5 [8]=negbce5 [9]=wincnt5
__device__ double g_acc[10];                  // zero-init; self-cleaned
__device__ unsigned int g_ticket;             // zero-init; self-cleaned
__device__ unsigned int g_gen = 1;            // generation tag (bumped each launch)
__device__ unsigned int g_cellgen[N4_ + N5_]; // zero-init; gen-tagged, never zeroed again

#define LOG2E 1.442695040888963f
#define LN2   0.6931471805599453f

__device__ __forceinline__ float bce0(float x) {   // log(1 + e^x), |x| small (<~10)
    return LN2 * __log2f(1.0f + exp2f(x * LOG2E));
}
__device__ __forceinline__ float bce1(float x) {   // log(1 + e^-x)
    return LN2 * __log2f(1.0f + exp2f(-x * LOG2E));
}

__global__ void __launch_bounds__(512) k_main(
    const float* __restrict__ cls4, const float* __restrict__ reg4,
    const float* __restrict__ cls5, const float* __restrict__ reg5,
    const float* __restrict__ tgt4, const float* __restrict__ tgt5,
    float* __restrict__ out)
{
    const int bx   = blockIdx.x;
    const int lane = threadIdx.x & 31;
    const int warp = threadIdx.x >> 5;

    __shared__ float sh[10][16];

    if (bx < NBT) {
        // ================= target blocks: 2 targets per warp =================
        if (threadIdx.x < 160) ((float*)sh)[threadIdx.x] = 0.0f;
        __syncthreads();

        const unsigned int gen = g_gen;

        // per-scale local accumulators (live in the lane that computes them)
        float sl1_4 = 0.f, cls_4 = 0.f, obj_4 = 0.f, cs_4 = 0.f, cc_4 = 0.f;
        float sl1_5 = 0.f, cls_5 = 0.f, obj_5 = 0.f, cs_5 = 0.f, cc_5 = 0.f;

        #pragma unroll
        for (int k = 0; k < 2; k++) {
            int widx = (bx * 16 + warp) * 2 + k;     // 0..9599
            bool is4 = (widx < NT4);
            int tw   = is4 ? widx : (widx - NT4);
            int b    = is4 ? (tw / T4_) : (tw / T5_);

            const int W  = is4 ? W4_ : W5_;
            const int H  = is4 ? H4_ : H5_;
            const int hw = is4 ? HW4 : HW5;
            const float* cls = is4 ? cls4 : cls5;
            const float* reg = is4 ? reg4 : reg5;
            const float* t   = (is4 ? tgt4 : tgt5) + (size_t)tw * 6;

            int   tcls = (int)t[0];
            float tx = t[1] * (float)W;
            float ty = t[2] * (float)H;
            float twd = t[3] * (float)W;
            float thd = t[4] * (float)H;

            int gx = min(max((int)tx, 0), W - 1);
            int gy = min(max((int)ty, 0), H - 1);
            int cell = gy * W + gx;
            size_t cb = (size_t)b * (1 + NC) * hw + cell;

            float v_sl1 = 0.f, v_cls = 0.f, v_obj = 0.f, v_cs = 0.f, v_cc = 0.f;

            if (lane < NC) {
                float x = cls[cb + (size_t)(lane + 1) * hw];
                float p = 1.0f / (1.0f + __expf(-x));
                bool hit = (lane == tcls);
                float bce = hit ? bce1(x) : bce0(x);
                float pt  = hit ? p : (1.0f - p);
                float om  = 1.0f - pt;
                v_cls = (0.25f / (float)NC) * om * om * bce;
            } else if (lane == 24) {
                float obj = cls[cb];
                v_obj = bce1(obj);
                // generation-tag dedup: winner iff first to stamp this cell
                int gcell = is4 ? (b * HW4 + cell) : (N4_ + b * HW5 + cell);
                unsigned int old = atomicExch(&g_cellgen[gcell], gen);
                if (old != gen) { v_cs = -bce0(obj); v_cc = 1.0f; }
            } else if (lane == 25) {
                size_t rb = (size_t)b * 4 * hw + cell;
                float r0 = reg[rb];
                float r1 = reg[rb + hw];
                float r2 = reg[rb + 2 * (size_t)hw];
                float r3 = reg[rb + 3 * (size_t)hw];
                float px = fminf(fmaxf((float)gx + r0, 0.0f), (float)W);
                float py = fminf(fmaxf((float)gy + r1, 0.0f), (float)H);
                float pw = fminf(fmaxf(__expf(r2), 1.0f), (float)W) * 0.1f;
                float ph = fminf(fmaxf(__expf(r3), 1.0f), (float)H) * 0.1f;
                float pb0 = px - pw * 0.5f, pb1 = py - ph * 0.5f;
                float pb2 = px + pw * 0.5f, pb3 = py + ph * 0.5f;
                float tb0 = tx - twd * 0.5f, tb1 = ty - thd * 0.5f;
                float tb2 = tx + twd * 0.5f, tb3 = ty + thd * 0.5f;
                float d, ad, s = 0.0f;
                d = pb0 - tb0; ad = fabsf(d); s += (ad < 1.0f) ? 0.5f * d * d : (ad - 0.5f);
                d = pb1 - tb1; ad = fabsf(d); s += (ad < 1.0f) ? 0.5f * d * d : (ad - 0.5f);
                d = pb2 - tb2; ad = fabsf(d); s += (ad < 1.0f) ? 0.5f * d * d : (ad - 0.5f);
                d = pb3 - tb3; ad = fabsf(d); s += (ad < 1.0f) ? 0.5f * d * d : (ad - 0.5f);
                v_sl1 = s * 0.25f;
            }

            if (is4) { sl1_4 += v_sl1; cls_4 += v_cls; obj_4 += v_obj; cs_4 += v_cs; cc_4 += v_cc; }
            else     { sl1_5 += v_sl1; cls_5 += v_cls; obj_5 += v_obj; cs_5 += v_cs; cc_5 += v_cc; }
        }

        // reduce focal across lanes (only lanes 0..23 nonzero)
        #pragma unroll
        for (int off = 16; off > 0; off >>= 1) {
            cls_4 += __shfl_down_sync(0xFFFFFFFFu, cls_4, off);
            cls_5 += __shfl_down_sync(0xFFFFFFFFu, cls_5, off);
        }

        if (lane == 0)  { sh[1][warp] = cls_4; sh[6][warp] = cls_5; }
        if (lane == 25) { sh[0][warp] = sl1_4; sh[5][warp] = sl1_5; }
        if (lane == 24) {
            sh[2][warp] = obj_4; sh[3][warp] = cs_4; sh[4][warp] = cc_4;
            sh[7][warp] = obj_5; sh[8][warp] = cs_5; sh[9][warp] = cc_5;
        }
        __syncthreads();

        if (warp < 10) {
            float a = (lane < 16) ? sh[warp][lane] : 0.0f;
            #pragma unroll
            for (int off = 8; off > 0; off >>= 1)
                a += __shfl_down_sync(0xFFFFFFFFu, a, off);
            if (lane == 0 && a != 0.0f) atomicAdd(&g_acc[warp], (double)a);
        }
    } else {
        // ================= streaming: sum bce(x,0) over all grid cells ======
        const int sbx = bx - NBT;
        const int tid = sbx * 512 + threadIdx.x;       // 0..81919
        const int NV4 = N4_ / 4;                       // 131072

        float s4 = 0.0f, s5 = 0.0f;
        {
            // vec 1: always in cls4 (tid < 81920 < 131072)
            int b = tid >> 12;
            int pos = (tid & 4095) * 4;
            const float4 x = *(const float4*)(cls4 + (size_t)b * (1 + NC) * HW4 + pos);
            s4 = bce0(x.x) + bce0(x.y) + bce0(x.z) + bce0(x.w);
        }
        {
            int v = tid + 81920;
            if (v < NV4) {
                int b = v >> 12;
                int pos = (v & 4095) * 4;
                const float4 x = *(const float4*)(cls4 + (size_t)b * (1 + NC) * HW4 + pos);
                s4 += bce0(x.x) + bce0(x.y) + bce0(x.z) + bce0(x.w);
            } else {
                int v5 = v - NV4;
                int b = v5 >> 10;
                int pos = (v5 & 1023) * 4;
                const float4 x = *(const float4*)(cls5 + (size_t)b * (1 + NC) * HW5 + pos);
                s5 += bce0(x.x) + bce0(x.y) + bce0(x.z) + bce0(x.w);
            }
        }
        #pragma unroll
        for (int off = 16; off > 0; off >>= 1) {
            s4 += __shfl_down_sync(0xFFFFFFFFu, s4, off);
            s5 += __shfl_down_sync(0xFFFFFFFFu, s5, off);
        }
        if (lane == 0) { sh[0][warp] = s4; sh[1][warp] = s5; }
        __syncthreads();
        if (warp == 0) {
            float a = (lane < 16) ? sh[0][lane] : 0.0f;
            float c = (lane < 16) ? sh[1][lane] : 0.0f;
            #pragma unroll
            for (int off = 8; off > 0; off >>= 1) {
                a += __shfl_down_sync(0xFFFFFFFFu, a, off);
                c += __shfl_down_sync(0xFFFFFFFFu, c, off);
            }
            if (lane == 0) {
                if (a != 0.0f) atomicAdd(&g_acc[3], (double)a);
                if (c != 0.0f) atomicAdd(&g_acc[8], (double)c);
            }
        }
    }

    // ================= last-block finalize (self-cleaning) ==================
    if (threadIdx.x == 0) {
        __threadfence();
        unsigned int old = atomicAdd(&g_ticket, 1u);
        if (old == NB_TOTAL - 1) {
            __threadfence();
            volatile double* acc = g_acc;
            double n  = (double)NTT;
            double lb = (acc[0] + acc[5]) / n;
            double lc = (acc[1] + acc[6]) / n;
            double cnt4 = (double)N4_ - acc[4];
            double cnt5 = (double)N5_ - acc[9];
            double lo4 = acc[2] + acc[3] / cnt4 * 0.5;
            double lo5 = acc[7] + acc[8] / cnt5 * 0.5;
            double lo = (lo4 + lo5) / ((double)(N4_ + N5_) + 1e-8);
            out[0] = (float)(lb + lo + lc);
            out[1] = (float)lb;
            out[2] = (float)lo;
            out[3] = (float)lc;
            #pragma unroll
            for (int i = 0; i < 10; i++) acc[i] = 0.0;
            g_gen = g_gen + 1u;                 // invalidate all cell tags
            __threadfence();
            *(volatile unsigned int*)&g_ticket = 0u;
        }
    }
}

extern "C" void kernel_launch(void* const* d_in, const int* in_sizes, int n_in,
                              void* d_out, int out_size) {
    const float* cls4 = (const float*)d_in[0];
    const float* reg4 = (const float*)d_in[1];
    const float* cls5 = (const float*)d_in[2];
    const float* reg5 = (const float*)d_in[3];
    const float* tgt4 = (const float*)d_in[4];
    const float* tgt5 = (const float*)d_in[5];
    float* out = (float*)d_out;

    k_main<<<NB_TOTAL, 512>>>(cls4, reg4, cls5, reg5, tgt4, tgt5, out);
}

// round 6
// speedup vs baseline: 5.7002x; 1.1597x over previous
#include <cuda_runtime.h>
#include <math.h>

#define NC 24
#define B_   32
#define H4_  128
#define W4_  128
#define H5_  64
#define W5_  64
#define T4_  200
#define T5_  100

#define HW4  (H4_*W4_)          // 16384
#define HW5  (H5_*W5_)          // 4096
#define N4_  (B_*HW4)           // 524288
#define N5_  (B_*HW5)           // 131072
#define NT4  (B_*T4_)           // 6400
#define NT5  (B_*T5_)           // 3200
#define NTT  (NT4+NT5)          // 9600

#define NFOCAL   (NTT*NC)                 // 230400
#define NTGT_END (NFOCAL+NTT)             // 240000
#define NSTREAM  ((N4_+N5_)/4)            // 163840
#define NTOTAL   (NTGT_END+NSTREAM)       // 403840

#define NB 740                            // blocks (256 thr)
#define NTHREADS (NB*256)                 // 189440

// g_acc: [0]=sl1 [1]=focal [2]=objpos [3]=nb4 [4]=wc4 [5]=nb5 [6]=wc5
__device__ double g_acc[7];                   // zero-init; self-cleaned
__device__ unsigned int g_ticket;             // zero-init; self-cleaned
__device__ unsigned int g_gen = 1;            // generation tag
__device__ unsigned int g_cellgen[N4_ + N5_]; // zero-init; gen-tagged

#define LOG2E 1.442695040888963f
#define LN2   0.6931471805599453f

__global__ void __launch_bounds__(256) k_main(
    const float* __restrict__ cls4, const float* __restrict__ reg4,
    const float* __restrict__ cls5, const float* __restrict__ reg5,
    const float* __restrict__ tgt4, const float* __restrict__ tgt5,
    float* __restrict__ out)
{
    const int lane = threadIdx.x & 31;
    const int warp = threadIdx.x >> 5;
    const unsigned int gen = g_gen;

    float a_sl1 = 0.f, a_fo = 0.f, a_ob = 0.f;
    float a_nb4 = 0.f, a_wc4 = 0.f, a_nb5 = 0.f, a_wc5 = 0.f;

    for (int i = blockIdx.x * 256 + threadIdx.x; i < NTOTAL; i += NTHREADS) {
        if (i < NFOCAL) {
            // ---------------- focal: one (target, class) per item -----------
            int t = i / NC;
            int c = i - t * NC;
            bool is4 = (t < NT4);
            int tl = is4 ? t : (t - NT4);
            int b  = is4 ? (tl / T4_) : (tl / T5_);
            const int W  = is4 ? W4_ : W5_;
            const int H  = is4 ? H4_ : H5_;
            const int hw = is4 ? HW4 : HW5;
            const float* tp = (is4 ? tgt4 : tgt5) + (size_t)tl * 6;
            const float* cls = is4 ? cls4 : cls5;

            int   tcls = (int)tp[0];
            float tx = tp[1] * (float)W;
            float ty = tp[2] * (float)H;
            int gx = min(max((int)tx, 0), W - 1);
            int gy = min(max((int)ty, 0), H - 1);
            int cell = gy * W + gx;

            float x = cls[(size_t)b * (1 + NC) * hw + (size_t)(c + 1) * hw + cell];
            float ax = fabsf(x);
            float s  = exp2f(-ax * LOG2E);          // e^{-|x|}
            float r  = __fdividef(1.0f, 1.0f + s);  // sigmoid(|x|)
            float l1p = LN2 * __log2f(1.0f + s);    // log1p(e^{-|x|})
            float sp = r, sn = s * r;               // sigmoid(+|x|), sigmoid(-|x|)
            bool hit = (c == tcls) && (tcls < NC);
            float bce = fmaxf(hit ? -x : x, 0.0f) + l1p;
            float sig_x  = (x >= 0.0f) ? sp : sn;   // sigmoid(x)
            float sig_mx = (x >= 0.0f) ? sn : sp;   // sigmoid(-x)
            float omp = hit ? sig_mx : sig_x;       // 1 - pt
            a_fo += (0.25f / (float)NC) * omp * omp * bce;
        } else if (i < NTGT_END) {
            // ---------------- per-target: objectness + dedup + bbox ---------
            int t = i - NFOCAL;
            bool is4 = (t < NT4);
            int tl = is4 ? t : (t - NT4);
            int b  = is4 ? (tl / T4_) : (tl / T5_);
            const int W  = is4 ? W4_ : W5_;
            const int H  = is4 ? H4_ : H5_;
            const int hw = is4 ? HW4 : HW5;
            const float* tp  = (is4 ? tgt4 : tgt5) + (size_t)tl * 6;
            const float* cls = is4 ? cls4 : cls5;
            const float* reg = is4 ? reg4 : reg5;

            float tx  = tp[1] * (float)W;
            float ty  = tp[2] * (float)H;
            float twd = tp[3] * (float)W;
            float thd = tp[4] * (float)H;
            int gx = min(max((int)tx, 0), W - 1);
            int gy = min(max((int)ty, 0), H - 1);
            int cell = gy * W + gx;

            // objectness
            float obj = cls[(size_t)b * (1 + NC) * hw + cell];
            float ao = fabsf(obj);
            float so = exp2f(-ao * LOG2E);
            float l1po = LN2 * __log2f(1.0f + so);
            a_ob += fmaxf(-obj, 0.0f) + l1po;       // bce(obj, 1)
            float bce0o = fmaxf(obj, 0.0f) + l1po;  // bce(obj, 0)

            // dedup via generation tag
            int gcell = is4 ? (b * HW4 + cell) : (N4_ + b * HW5 + cell);
            unsigned int old = atomicExch(&g_cellgen[gcell], gen);
            if (old != gen) {
                if (is4) { a_nb4 -= bce0o; a_wc4 += 1.0f; }
                else     { a_nb5 -= bce0o; a_wc5 += 1.0f; }
            }

            // bbox smooth-L1
            size_t rb = (size_t)b * 4 * hw + cell;
            float r0 = reg[rb];
            float r1 = reg[rb + hw];
            float r2 = reg[rb + 2 * (size_t)hw];
            float r3 = reg[rb + 3 * (size_t)hw];
            float px = fminf(fmaxf((float)gx + r0, 0.0f), (float)W);
            float py = fminf(fmaxf((float)gy + r1, 0.0f), (float)H);
            float pw = fminf(fmaxf(__expf(r2), 1.0f), (float)W) * 0.1f;
            float ph = fminf(fmaxf(__expf(r3), 1.0f), (float)H) * 0.1f;
            float d, ad, sl = 0.0f;
            d = (px - pw * 0.5f) - (tx - twd * 0.5f); ad = fabsf(d);
            sl += (ad < 1.0f) ? 0.5f * d * d : (ad - 0.5f);
            d = (py - ph * 0.5f) - (ty - thd * 0.5f); ad = fabsf(d);
            sl += (ad < 1.0f) ? 0.5f * d * d : (ad - 0.5f);
            d = (px + pw * 0.5f) - (tx + twd * 0.5f); ad = fabsf(d);
            sl += (ad < 1.0f) ? 0.5f * d * d : (ad - 0.5f);
            d = (py + ph * 0.5f) - (ty + thd * 0.5f); ad = fabsf(d);
            sl += (ad < 1.0f) ? 0.5f * d * d : (ad - 0.5f);
            a_sl1 += sl * 0.25f;
        } else {
            // ---------------- streaming negatives: one float4 per item ------
            int v = i - NTGT_END;
            const int NV4 = N4_ / 4;
            float4 x;
            bool is4 = (v < NV4);
            if (is4) {
                int b = v >> 12;
                int pos = (v & 4095) * 4;
                x = *(const float4*)(cls4 + (size_t)b * (1 + NC) * HW4 + pos);
            } else {
                int v5 = v - NV4;
                int b = v5 >> 10;
                int pos = (v5 & 1023) * 4;
                x = *(const float4*)(cls5 + (size_t)b * (1 + NC) * HW5 + pos);
            }
            // sum of bce(x,0) = sum max(x,0) + log(prod(1 + e^{-|x|}))
            float m = fmaxf(x.x, 0.0f) + fmaxf(x.y, 0.0f) +
                      fmaxf(x.z, 0.0f) + fmaxf(x.w, 0.0f);
            float p0 = 1.0f + exp2f(-fabsf(x.x) * LOG2E);
            float p1 = 1.0f + exp2f(-fabsf(x.y) * LOG2E);
            float p2 = 1.0f + exp2f(-fabsf(x.z) * LOG2E);
            float p3 = 1.0f + exp2f(-fabsf(x.w) * LOG2E);
            float sum = m + LN2 * __log2f((p0 * p1) * (p2 * p3));
            if (is4) a_nb4 += sum; else a_nb5 += sum;
        }
    }

    // ---------------- block reduction of 7 accumulators ----------------------
    __shared__ float sh[7][8];
    #pragma unroll
    for (int off = 16; off > 0; off >>= 1) {
        a_sl1 += __shfl_down_sync(0xFFFFFFFFu, a_sl1, off);
        a_fo  += __shfl_down_sync(0xFFFFFFFFu, a_fo,  off);
        a_ob  += __shfl_down_sync(0xFFFFFFFFu, a_ob,  off);
        a_nb4 += __shfl_down_sync(0xFFFFFFFFu, a_nb4, off);
        a_wc4 += __shfl_down_sync(0xFFFFFFFFu, a_wc4, off);
        a_nb5 += __shfl_down_sync(0xFFFFFFFFu, a_nb5, off);
        a_wc5 += __shfl_down_sync(0xFFFFFFFFu, a_wc5, off);
    }
    if (lane == 0) {
        sh[0][warp] = a_sl1; sh[1][warp] = a_fo;  sh[2][warp] = a_ob;
        sh[3][warp] = a_nb4; sh[4][warp] = a_wc4;
        sh[5][warp] = a_nb5; sh[6][warp] = a_wc5;
    }
    __syncthreads();
    if (warp < 7) {
        float a = (lane < 8) ? sh[warp][lane] : 0.0f;
        #pragma unroll
        for (int off = 4; off > 0; off >>= 1)
            a += __shfl_down_sync(0xFFFFFFFFu, a, off);
        if (lane == 0 && a != 0.0f) atomicAdd(&g_acc[warp], (double)a);
    }

    // ---------------- last-block finalize (self-cleaning) --------------------
    if (threadIdx.x == 0) {
        __threadfence();
        unsigned int old = atomicAdd(&g_ticket, 1u);
        if (old == NB - 1) {
            __threadfence();
            volatile double* acc = g_acc;
            double n  = (double)NTT;
            double lb = acc[0] / n;
            double lc = acc[1] / n;
            double lo4p = acc[3] / ((double)N4_ - acc[4]);
            double lo5p = acc[5] / ((double)N5_ - acc[6]);
            double lo = (acc[2] + 0.5 * (lo4p + lo5p)) / ((double)(N4_ + N5_) + 1e-8);
            out[0] = (float)(lb + lo + lc);
            out[1] = (float)lb;
            out[2] = (float)lo;
            out[3] = (float)lc;
            #pragma unroll
            for (int k = 0; k < 7; k++) acc[k] = 0.0;
            g_gen = g_gen + 1u;
            __threadfence();
            *(volatile unsigned int*)&g_ticket = 0u;
        }
    }
}

extern "C" void kernel_launch(void* const* d_in, const int* in_sizes, int n_in,
                              void* d_out, int out_size) {
    const float* cls4 = (const float*)d_in[0];
    const float* reg4 = (const float*)d_in[1];
    const float* cls5 = (const float*)d_in[2];
    const float* reg5 = (const float*)d_in[3];
    const float* tgt4 = (const float*)d_in[4];
    const float* tgt5 = (const float*)d_in[5];
    float* out = (float*)d_out;

    k_main<<<NB, 256>>>(cls4, reg4, cls5, reg5, tgt4, tgt5, out);
}